// round 1
// baseline (speedup 1.0000x reference)
#include <cuda_runtime.h>
#include <cuda_bf16.h>
#include <math.h>

// ============================================================================
// Attention block: x@Wq/Wk/Wv -> RoPE -> causal GQA flash attention -> @Wo
// B=2, S=2048, D=4096, H=32, KVH=8, HD=128. All fp32.
// ============================================================================

#define BSZ 2
#define SEQ 2048
#define DIM 4096
#define NH 32
#define NKVH 8
#define HD 128
#define MROWS (BSZ*SEQ)          // 4096

// Scratch (device globals; allocation in kernel_launch is forbidden)
__device__ float g_q[(size_t)BSZ*NH*SEQ*HD];      // [B,H,S,HD]   64MB
__device__ float g_k[(size_t)BSZ*NKVH*SEQ*HD];    // [B,KVH,S,HD] 16MB
__device__ float g_v[(size_t)BSZ*NKVH*SEQ*HD];    // 16MB
__device__ float g_attn[(size_t)MROWS*DIM];       // [B*S, H*HD]  64MB

// ----------------------------------------------------------------------------
// SGEMM: C = A[M,K] @ B[K,N], row-major fp32. 128x128 tile, BK=16, 256 thr,
// 8x8 per thread (split 4+4 halves). out_mode 0: plain row-major.
// out_mode 1: split heads -> [B, nheads, S, HD] layout.
// ----------------------------------------------------------------------------
#define BM 128
#define BN 128
#define BK 16

__global__ __launch_bounds__(256) void sgemm_kernel(
    const float* __restrict__ A, const float* __restrict__ Bm,
    float* __restrict__ C, int M, int N, int K, int out_mode, int nheads)
{
    __shared__ float As[BK][BM + 4];
    __shared__ float Bs[BK][BN + 4];

    const int tid = threadIdx.x;
    const int bn = blockIdx.x * BN;
    const int bm = blockIdx.y * BM;
    const int tx = tid & 15;   // col group
    const int ty = tid >> 4;   // row group

    float acc[8][8];
    #pragma unroll
    for (int i = 0; i < 8; i++)
        #pragma unroll
        for (int j = 0; j < 8; j++) acc[i][j] = 0.f;

    for (int k0 = 0; k0 < K; k0 += BK) {
        // Load A tile (BM x BK): 512 float4, 2 per thread, transpose into As
        #pragma unroll
        for (int i = 0; i < 2; i++) {
            int f = tid + i * 256;
            int r = f >> 2;              // 0..127
            int cv = (f & 3) << 2;       // 0,4,8,12
            float4 v = *(const float4*)(A + (size_t)(bm + r) * K + k0 + cv);
            As[cv + 0][r] = v.x;
            As[cv + 1][r] = v.y;
            As[cv + 2][r] = v.z;
            As[cv + 3][r] = v.w;
        }
        // Load B tile (BK x BN): 512 float4, 2 per thread
        #pragma unroll
        for (int i = 0; i < 2; i++) {
            int f = tid + i * 256;
            int r = f >> 5;              // 0..15
            int cv = (f & 31) << 2;      // 0..124
            *(float4*)(&Bs[r][cv]) =
                *(const float4*)(Bm + (size_t)(k0 + r) * N + bn + cv);
        }
        __syncthreads();

        #pragma unroll
        for (int k = 0; k < BK; k++) {
            float a[8], b[8];
            #pragma unroll
            for (int i = 0; i < 4; i++) {
                a[i]     = As[k][ty * 4 + i];
                a[4 + i] = As[k][64 + ty * 4 + i];
                b[i]     = Bs[k][tx * 4 + i];
                b[4 + i] = Bs[k][64 + tx * 4 + i];
            }
            #pragma unroll
            for (int i = 0; i < 8; i++)
                #pragma unroll
                for (int j = 0; j < 8; j++)
                    acc[i][j] += a[i] * b[j];
        }
        __syncthreads();
    }

    // Epilogue
    #pragma unroll
    for (int i = 0; i < 8; i++) {
        int r = bm + ((i < 4) ? (ty * 4 + i) : (64 + ty * 4 + i - 4));
        #pragma unroll
        for (int j = 0; j < 8; j++) {
            int c = bn + ((j < 4) ? (tx * 4 + j) : (64 + tx * 4 + j - 4));
            float v = acc[i][j];
            if (out_mode == 0) {
                C[(size_t)r * N + c] = v;
            } else {
                int b_ = r >> 11, s = r & 2047;
                int h = c >> 7, d = c & 127;
                C[(((size_t)b_ * nheads + h) * SEQ + s) * HD + d] = v;
            }
        }
    }
}

// ----------------------------------------------------------------------------
// RoPE in-place over g_q ([B,H,S,HD]) and g_k ([B,KVH,S,HD]).
// One thread per (row, pair).
// ----------------------------------------------------------------------------
__global__ void rope_kernel(float* __restrict__ qb, float* __restrict__ kb,
                            const float* __restrict__ cosb,
                            const float* __restrict__ sinb)
{
    size_t i = (size_t)blockIdx.x * blockDim.x + threadIdx.x;
    const size_t QP = (size_t)BSZ * NH * SEQ * 64;
    const size_t KP = (size_t)BSZ * NKVH * SEQ * 64;
    float* base;
    size_t idx;
    if (i < QP)            { base = qb; idx = i; }
    else if (i < QP + KP)  { base = kb; idx = i - QP; }
    else return;
    size_t row = idx >> 6;
    int p = (int)(idx & 63);
    int s = (int)(row & (SEQ - 1));
    float c  = cosb[s * 64 + p];
    float sn = sinb[s * 64 + p];
    float2* ptr = (float2*)(base + row * HD) + p;
    float2 v = *ptr;
    *ptr = make_float2(v.x * c - v.y * sn, v.x * sn + v.y * c);
}

// ----------------------------------------------------------------------------
// Flash attention, fp32. Block: 128 query rows x one (b,h). 256 threads.
// K/V tiles of 64 rows streamed through smem with XOR-swizzled float4 layout
// (slot(r,dv) = r*32 + (dv ^ ((r>>3)&7))) for conflict-free row-strided reads.
// Thread (rg=tid>>3, cg=tid&7): scores 4 rows x 8 keys; PV 4 rows x 16 cols.
// ----------------------------------------------------------------------------
#define AQ 128   // query rows per block
#define AK 64    // key rows per tile
#define PS_STRIDE 65

__device__ __forceinline__ int swz(int r, int dv) {
    return (r * 32 + (dv ^ ((r >> 3) & 7))) * 4;
}

__global__ __launch_bounds__(256) void attn_kernel(
    const float* __restrict__ qb, const float* __restrict__ kb,
    const float* __restrict__ vb, float* __restrict__ outb)
{
    extern __shared__ float sm[];
    float* Qs    = sm;                     // 128*128
    float* Ks    = Qs + AQ * HD;           // 64*128
    float* Vs    = Ks + AK * HD;           // 64*128
    float* Ps    = Vs + AK * HD;           // 128*65
    float* rowm  = Ps + AQ * PS_STRIDE;    // 128
    float* rowl  = rowm + AQ;              // 128
    float* rowsc = rowl + AQ;              // 128

    const int qt = blockIdx.x;   // 0..15
    const int h  = blockIdx.y;   // 0..31
    const int b  = blockIdx.z;   // 0..1
    const int kvh = h >> 2;
    const int tid = threadIdx.x;
    const int rg = tid >> 3;     // 0..31 -> rows rg*4..+3
    const int cg = tid & 7;      // 0..7

    const float* qsrc = qb + (((size_t)(b * NH + h)) * SEQ + (size_t)qt * AQ) * HD;
    const float* ksrc = kb + ((size_t)(b * NKVH + kvh)) * SEQ * HD;
    const float* vsrc = vb + ((size_t)(b * NKVH + kvh)) * SEQ * HD;

    // Load Q tile (128x128 floats = 4096 float4 / 256 thr = 16 each)
    for (int f = tid; f < AQ * 32; f += 256) {
        int r = f >> 5, dv = f & 31;
        float4 v = *(const float4*)(qsrc + (size_t)r * HD + dv * 4);
        *(float4*)(Qs + swz(r, dv)) = v;
    }
    if (tid < AQ) { rowm[tid] = -1e30f; rowl[tid] = 0.f; }

    float O[4][16];
    #pragma unroll
    for (int i = 0; i < 4; i++)
        #pragma unroll
        for (int j = 0; j < 16; j++) O[i][j] = 0.f;

    const int nkt = 2 * qt + 2;
    const float scale = 0.08838834764831845f;   // 1/sqrt(128)

    for (int kt = 0; kt < nkt; kt++) {
        __syncthreads();
        // Load K,V tile (each 64x128 = 2048 float4 / 256 thr = 8 each)
        const float* kts = ksrc + (size_t)kt * AK * HD;
        const float* vts = vsrc + (size_t)kt * AK * HD;
        for (int f = tid; f < AK * 32; f += 256) {
            int r = f >> 5, dv = f & 31;
            int so = swz(r, dv);
            *(float4*)(Ks + so) = *(const float4*)(kts + (size_t)r * HD + dv * 4);
            *(float4*)(Vs + so) = *(const float4*)(vts + (size_t)r * HD + dv * 4);
        }
        __syncthreads();

        // Scores: 4 rows x 8 keys per thread
        float acc[4][8];
        #pragma unroll
        for (int i = 0; i < 4; i++)
            #pragma unroll
            for (int j = 0; j < 8; j++) acc[i][j] = 0.f;

        #pragma unroll 4
        for (int d4 = 0; d4 < 32; d4++) {
            float4 aq[4], bk[8];
            #pragma unroll
            for (int i = 0; i < 4; i++) {
                int r = rg * 4 + i;
                aq[i] = *(const float4*)(Qs + swz(r, d4));
            }
            #pragma unroll
            for (int j = 0; j < 8; j++) {
                int r = cg * 8 + j;
                bk[j] = *(const float4*)(Ks + swz(r, d4));
            }
            #pragma unroll
            for (int i = 0; i < 4; i++)
                #pragma unroll
                for (int j = 0; j < 8; j++)
                    acc[i][j] += aq[i].x * bk[j].x + aq[i].y * bk[j].y +
                                 aq[i].z * bk[j].z + aq[i].w * bk[j].w;
        }

        // Online softmax per row (octet = 8 consecutive lanes share a row set)
        const bool diag = (kt >= 2 * qt);
        #pragma unroll
        for (int i = 0; i < 4; i++) {
            int r = rg * 4 + i;
            int qg = qt * AQ + r;
            float sc[8];
            float mx = -1e30f;
            #pragma unroll
            for (int j = 0; j < 8; j++) {
                float s = acc[i][j] * scale;
                if (diag && (kt * AK + cg * 8 + j) > qg) s = -1e30f;
                sc[j] = s;
                mx = fmaxf(mx, s);
            }
            #pragma unroll
            for (int o = 1; o < 8; o <<= 1)
                mx = fmaxf(mx, __shfl_xor_sync(0xffffffffu, mx, o));
            float m_old = rowm[r];
            float m_new = fmaxf(m_old, mx);
            float lsum = 0.f;
            #pragma unroll
            for (int j = 0; j < 8; j++) {
                float p = __expf(sc[j] - m_new);
                Ps[r * PS_STRIDE + cg * 8 + j] = p;
                lsum += p;
            }
            #pragma unroll
            for (int o = 1; o < 8; o <<= 1)
                lsum += __shfl_xor_sync(0xffffffffu, lsum, o);
            if (cg == 0) {
                float rsc = __expf(m_old - m_new);
                rowm[r] = m_new;
                rowl[r] = rowl[r] * rsc + lsum;
                rowsc[r] = rsc;
            }
        }
        __syncthreads();

        // Rescale O, then PV accumulate: 4 rows x 16 cols per thread
        #pragma unroll
        for (int i = 0; i < 4; i++) {
            float rsc = rowsc[rg * 4 + i];
            #pragma unroll
            for (int j = 0; j < 16; j++) O[i][j] *= rsc;
        }
        #pragma unroll 4
        for (int k = 0; k < AK; k++) {
            float4 v0 = *(const float4*)(Vs + swz(k, cg * 4 + 0));
            float4 v1 = *(const float4*)(Vs + swz(k, cg * 4 + 1));
            float4 v2 = *(const float4*)(Vs + swz(k, cg * 4 + 2));
            float4 v3 = *(const float4*)(Vs + swz(k, cg * 4 + 3));
            #pragma unroll
            for (int i = 0; i < 4; i++) {
                float p = Ps[(rg * 4 + i) * PS_STRIDE + k];
                O[i][0]  += p * v0.x; O[i][1]  += p * v0.y;
                O[i][2]  += p * v0.z; O[i][3]  += p * v0.w;
                O[i][4]  += p * v1.x; O[i][5]  += p * v1.y;
                O[i][6]  += p * v1.z; O[i][7]  += p * v1.w;
                O[i][8]  += p * v2.x; O[i][9]  += p * v2.y;
                O[i][10] += p * v2.z; O[i][11] += p * v2.w;
                O[i][12] += p * v3.x; O[i][13] += p * v3.y;
                O[i][14] += p * v3.z; O[i][15] += p * v3.w;
            }
        }
    }

    // Epilogue: O / l -> g_attn[b*S + s][h*HD + c]
    #pragma unroll
    for (int i = 0; i < 4; i++) {
        int r = rg * 4 + i;
        float inv = 1.0f / rowl[r];
        int srow = qt * AQ + r;
        float* dst = outb + ((size_t)(b * SEQ + srow)) * DIM + h * HD + cg * 16;
        float4 o0 = make_float4(O[i][0] * inv, O[i][1] * inv, O[i][2] * inv, O[i][3] * inv);
        float4 o1 = make_float4(O[i][4] * inv, O[i][5] * inv, O[i][6] * inv, O[i][7] * inv);
        float4 o2 = make_float4(O[i][8] * inv, O[i][9] * inv, O[i][10] * inv, O[i][11] * inv);
        float4 o3 = make_float4(O[i][12] * inv, O[i][13] * inv, O[i][14] * inv, O[i][15] * inv);
        *(float4*)(dst + 0)  = o0;
        *(float4*)(dst + 4)  = o1;
        *(float4*)(dst + 8)  = o2;
        *(float4*)(dst + 12) = o3;
    }
}

// ----------------------------------------------------------------------------
// Host launcher
// ----------------------------------------------------------------------------
extern "C" void kernel_launch(void* const* d_in, const int* in_sizes, int n_in,
                              void* d_out, int out_size)
{
    // Input order: x, start_pos, freqs_cos, freqs_sin, mask, wq, wk, wv, wo,
    //              cache_k, cache_v. start_pos==0 -> mask/caches unused.
    const float* x  = (const float*)d_in[0];
    const float* fc = (const float*)d_in[2];
    const float* fs = (const float*)d_in[3];
    const float* wq = (const float*)d_in[5];
    const float* wk = (const float*)d_in[6];
    const float* wv = (const float*)d_in[7];
    const float* wo = (const float*)d_in[8];
    float* out = (float*)d_out;

    float *gq, *gk, *gv, *gattn;
    cudaGetSymbolAddress((void**)&gq, g_q);
    cudaGetSymbolAddress((void**)&gk, g_k);
    cudaGetSymbolAddress((void**)&gv, g_v);
    cudaGetSymbolAddress((void**)&gattn, g_attn);

    // QKV projections (epilogue splits heads into [B, nh, S, HD])
    sgemm_kernel<<<dim3(DIM / BN, MROWS / BM), 256>>>(x, wq, gq, MROWS, DIM, DIM, 1, NH);
    sgemm_kernel<<<dim3((NKVH * HD) / BN, MROWS / BM), 256>>>(x, wk, gk, MROWS, NKVH * HD, DIM, 1, NKVH);
    sgemm_kernel<<<dim3((NKVH * HD) / BN, MROWS / BM), 256>>>(x, wv, gv, MROWS, NKVH * HD, DIM, 1, NKVH);

    // RoPE on Q and K
    {
        size_t total = (size_t)BSZ * (NH + NKVH) * SEQ * 64;
        int blocks = (int)((total + 255) / 256);
        rope_kernel<<<blocks, 256>>>(gq, gk, fc, fs);
    }

    // Flash attention
    {
        const int smem = (AQ * HD + AK * HD + AK * HD + AQ * PS_STRIDE + 3 * AQ) * 4;
        cudaFuncSetAttribute(attn_kernel, cudaFuncAttributeMaxDynamicSharedMemorySize, smem);
        attn_kernel<<<dim3(SEQ / AQ, NH, BSZ), 256, smem>>>(gq, gk, gv, gattn);
    }

    // Output projection
    sgemm_kernel<<<dim3(DIM / BN, MROWS / BM), 256>>>(gattn, wo, out, MROWS, DIM, DIM, 0, 0);
}

// round 2
// speedup vs baseline: 1.0009x; 1.0009x over previous
#include <cuda_runtime.h>
#include <cuda_bf16.h>
#include <math.h>

// ============================================================================
// Attention block: x@Wq/Wk/Wv -> RoPE -> causal GQA flash attention -> @Wo
// B=2, S=2048, D=4096, H=32, KVH=8, HD=128. All fp32.
// ============================================================================

#define BSZ 2
#define SEQ 2048
#define DIM 4096
#define NH 32
#define NKVH 8
#define HD 128
#define MROWS (BSZ*SEQ)          // 4096

// Scratch (device globals; allocation in kernel_launch is forbidden)
__device__ float g_q[(size_t)BSZ*NH*SEQ*HD];      // [B,H,S,HD]   64MB
__device__ float g_k[(size_t)BSZ*NKVH*SEQ*HD];    // [B,KVH,S,HD] 16MB
__device__ float g_v[(size_t)BSZ*NKVH*SEQ*HD];    // 16MB
__device__ float g_attn[(size_t)MROWS*DIM];       // [B*S, H*HD]  64MB

// ----------------------------------------------------------------------------
// SGEMM: C = A[M,K] @ B[K,N], row-major fp32. 128x128 tile, BK=16, 256 thr,
// 8x8 per thread (split 4+4 halves). out_mode 0: plain row-major.
// out_mode 1: split heads -> [B, nheads, S, HD] layout.
// ----------------------------------------------------------------------------
#define BM 128
#define BN 128
#define BK 16

__global__ __launch_bounds__(256) void sgemm_kernel(
    const float* __restrict__ A, const float* __restrict__ Bm,
    float* __restrict__ C, int M, int N, int K, int out_mode, int nheads)
{
    __shared__ float As[BK][BM + 4];
    __shared__ float Bs[BK][BN + 4];

    const int tid = threadIdx.x;
    const int bn = blockIdx.x * BN;
    const int bm = blockIdx.y * BM;
    const int tx = tid & 15;   // col group
    const int ty = tid >> 4;   // row group

    float acc[8][8];
    #pragma unroll
    for (int i = 0; i < 8; i++)
        #pragma unroll
        for (int j = 0; j < 8; j++) acc[i][j] = 0.f;

    for (int k0 = 0; k0 < K; k0 += BK) {
        // Load A tile (BM x BK): 512 float4, 2 per thread, transpose into As
        #pragma unroll
        for (int i = 0; i < 2; i++) {
            int f = tid + i * 256;
            int r = f >> 2;              // 0..127
            int cv = (f & 3) << 2;       // 0,4,8,12
            float4 v = *(const float4*)(A + (size_t)(bm + r) * K + k0 + cv);
            As[cv + 0][r] = v.x;
            As[cv + 1][r] = v.y;
            As[cv + 2][r] = v.z;
            As[cv + 3][r] = v.w;
        }
        // Load B tile (BK x BN): 512 float4, 2 per thread
        #pragma unroll
        for (int i = 0; i < 2; i++) {
            int f = tid + i * 256;
            int r = f >> 5;              // 0..15
            int cv = (f & 31) << 2;      // 0..124
            *(float4*)(&Bs[r][cv]) =
                *(const float4*)(Bm + (size_t)(k0 + r) * N + bn + cv);
        }
        __syncthreads();

        #pragma unroll
        for (int k = 0; k < BK; k++) {
            float a[8], b[8];
            #pragma unroll
            for (int i = 0; i < 4; i++) {
                a[i]     = As[k][ty * 4 + i];
                a[4 + i] = As[k][64 + ty * 4 + i];
                b[i]     = Bs[k][tx * 4 + i];
                b[4 + i] = Bs[k][64 + tx * 4 + i];
            }
            #pragma unroll
            for (int i = 0; i < 8; i++)
                #pragma unroll
                for (int j = 0; j < 8; j++)
                    acc[i][j] += a[i] * b[j];
        }
        __syncthreads();
    }

    // Epilogue
    #pragma unroll
    for (int i = 0; i < 8; i++) {
        int r = bm + ((i < 4) ? (ty * 4 + i) : (64 + ty * 4 + i - 4));
        #pragma unroll
        for (int j = 0; j < 8; j++) {
            int c = bn + ((j < 4) ? (tx * 4 + j) : (64 + tx * 4 + j - 4));
            float v = acc[i][j];
            if (out_mode == 0) {
                C[(size_t)r * N + c] = v;
            } else {
                int b_ = r >> 11, s = r & 2047;
                int h = c >> 7, d = c & 127;
                C[(((size_t)b_ * nheads + h) * SEQ + s) * HD + d] = v;
            }
        }
    }
}

// ----------------------------------------------------------------------------
// RoPE in-place over g_q ([B,H,S,HD]) and g_k ([B,KVH,S,HD]).
// One thread per (row, pair).
// ----------------------------------------------------------------------------
__global__ void rope_kernel(float* __restrict__ qb, float* __restrict__ kb,
                            const float* __restrict__ cosb,
                            const float* __restrict__ sinb)
{
    size_t i = (size_t)blockIdx.x * blockDim.x + threadIdx.x;
    const size_t QP = (size_t)BSZ * NH * SEQ * 64;
    const size_t KP = (size_t)BSZ * NKVH * SEQ * 64;
    float* base;
    size_t idx;
    if (i < QP)            { base = qb; idx = i; }
    else if (i < QP + KP)  { base = kb; idx = i - QP; }
    else return;
    size_t row = idx >> 6;
    int p = (int)(idx & 63);
    int s = (int)(row & (SEQ - 1));
    float c  = cosb[s * 64 + p];
    float sn = sinb[s * 64 + p];
    float2* ptr = (float2*)(base + row * HD) + p;
    float2 v = *ptr;
    *ptr = make_float2(v.x * c - v.y * sn, v.x * sn + v.y * c);
}

// ----------------------------------------------------------------------------
// Flash attention, fp32. Block: 128 query rows x one (b,h). 256 threads.
// K/V tiles of 64 rows streamed through smem with XOR-swizzled float4 layout
// (slot(r,dv) = r*32 + (dv ^ ((r>>3)&7))) for conflict-free row-strided reads.
// Thread (rg=tid>>3, cg=tid&7): scores 4 rows x 8 keys; PV 4 rows x 16 cols.
// ----------------------------------------------------------------------------
#define AQ 128   // query rows per block
#define AK 64    // key rows per tile
#define PS_STRIDE 65

__device__ __forceinline__ int swz(int r, int dv) {
    return (r * 32 + (dv ^ ((r >> 3) & 7))) * 4;
}

__global__ __launch_bounds__(256) void attn_kernel(
    const float* __restrict__ qb, const float* __restrict__ kb,
    const float* __restrict__ vb, float* __restrict__ outb)
{
    extern __shared__ float sm[];
    float* Qs    = sm;                     // 128*128
    float* Ks    = Qs + AQ * HD;           // 64*128
    float* Vs    = Ks + AK * HD;           // 64*128
    float* Ps    = Vs + AK * HD;           // 128*65
    float* rowm  = Ps + AQ * PS_STRIDE;    // 128
    float* rowl  = rowm + AQ;              // 128
    float* rowsc = rowl + AQ;              // 128

    const int qt = blockIdx.x;   // 0..15
    const int h  = blockIdx.y;   // 0..31
    const int b  = blockIdx.z;   // 0..1
    const int kvh = h >> 2;
    const int tid = threadIdx.x;
    const int rg = tid >> 3;     // 0..31 -> rows rg*4..+3
    const int cg = tid & 7;      // 0..7

    const float* qsrc = qb + (((size_t)(b * NH + h)) * SEQ + (size_t)qt * AQ) * HD;
    const float* ksrc = kb + ((size_t)(b * NKVH + kvh)) * SEQ * HD;
    const float* vsrc = vb + ((size_t)(b * NKVH + kvh)) * SEQ * HD;

    // Load Q tile (128x128 floats = 4096 float4 / 256 thr = 16 each)
    for (int f = tid; f < AQ * 32; f += 256) {
        int r = f >> 5, dv = f & 31;
        float4 v = *(const float4*)(qsrc + (size_t)r * HD + dv * 4);
        *(float4*)(Qs + swz(r, dv)) = v;
    }
    if (tid < AQ) { rowm[tid] = -1e30f; rowl[tid] = 0.f; }

    float O[4][16];
    #pragma unroll
    for (int i = 0; i < 4; i++)
        #pragma unroll
        for (int j = 0; j < 16; j++) O[i][j] = 0.f;

    const int nkt = 2 * qt + 2;
    const float scale = 0.08838834764831845f;   // 1/sqrt(128)

    for (int kt = 0; kt < nkt; kt++) {
        __syncthreads();
        // Load K,V tile (each 64x128 = 2048 float4 / 256 thr = 8 each)
        const float* kts = ksrc + (size_t)kt * AK * HD;
        const float* vts = vsrc + (size_t)kt * AK * HD;
        for (int f = tid; f < AK * 32; f += 256) {
            int r = f >> 5, dv = f & 31;
            int so = swz(r, dv);
            *(float4*)(Ks + so) = *(const float4*)(kts + (size_t)r * HD + dv * 4);
            *(float4*)(Vs + so) = *(const float4*)(vts + (size_t)r * HD + dv * 4);
        }
        __syncthreads();

        // Scores: 4 rows x 8 keys per thread
        float acc[4][8];
        #pragma unroll
        for (int i = 0; i < 4; i++)
            #pragma unroll
            for (int j = 0; j < 8; j++) acc[i][j] = 0.f;

        #pragma unroll 4
        for (int d4 = 0; d4 < 32; d4++) {
            float4 aq[4], bk[8];
            #pragma unroll
            for (int i = 0; i < 4; i++) {
                int r = rg * 4 + i;
                aq[i] = *(const float4*)(Qs + swz(r, d4));
            }
            #pragma unroll
            for (int j = 0; j < 8; j++) {
                int r = cg * 8 + j;
                bk[j] = *(const float4*)(Ks + swz(r, d4));
            }
            #pragma unroll
            for (int i = 0; i < 4; i++)
                #pragma unroll
                for (int j = 0; j < 8; j++)
                    acc[i][j] += aq[i].x * bk[j].x + aq[i].y * bk[j].y +
                                 aq[i].z * bk[j].z + aq[i].w * bk[j].w;
        }

        // Online softmax per row (octet = 8 consecutive lanes share a row set)
        const bool diag = (kt >= 2 * qt);
        #pragma unroll
        for (int i = 0; i < 4; i++) {
            int r = rg * 4 + i;
            int qg = qt * AQ + r;
            float sc[8];
            float mx = -1e30f;
            #pragma unroll
            for (int j = 0; j < 8; j++) {
                float s = acc[i][j] * scale;
                if (diag && (kt * AK + cg * 8 + j) > qg) s = -1e30f;
                sc[j] = s;
                mx = fmaxf(mx, s);
            }
            #pragma unroll
            for (int o = 1; o < 8; o <<= 1)
                mx = fmaxf(mx, __shfl_xor_sync(0xffffffffu, mx, o));
            float m_old = rowm[r];
            float m_new = fmaxf(m_old, mx);
            float lsum = 0.f;
            #pragma unroll
            for (int j = 0; j < 8; j++) {
                float p = __expf(sc[j] - m_new);
                Ps[r * PS_STRIDE + cg * 8 + j] = p;
                lsum += p;
            }
            #pragma unroll
            for (int o = 1; o < 8; o <<= 1)
                lsum += __shfl_xor_sync(0xffffffffu, lsum, o);
            if (cg == 0) {
                float rsc = __expf(m_old - m_new);
                rowm[r] = m_new;
                rowl[r] = rowl[r] * rsc + lsum;
                rowsc[r] = rsc;
            }
        }
        __syncthreads();

        // Rescale O, then PV accumulate: 4 rows x 16 cols per thread
        #pragma unroll
        for (int i = 0; i < 4; i++) {
            float rsc = rowsc[rg * 4 + i];
            #pragma unroll
            for (int j = 0; j < 16; j++) O[i][j] *= rsc;
        }
        #pragma unroll 4
        for (int k = 0; k < AK; k++) {
            float4 v0 = *(const float4*)(Vs + swz(k, cg * 4 + 0));
            float4 v1 = *(const float4*)(Vs + swz(k, cg * 4 + 1));
            float4 v2 = *(const float4*)(Vs + swz(k, cg * 4 + 2));
            float4 v3 = *(const float4*)(Vs + swz(k, cg * 4 + 3));
            #pragma unroll
            for (int i = 0; i < 4; i++) {
                float p = Ps[(rg * 4 + i) * PS_STRIDE + k];
                O[i][0]  += p * v0.x; O[i][1]  += p * v0.y;
                O[i][2]  += p * v0.z; O[i][3]  += p * v0.w;
                O[i][4]  += p * v1.x; O[i][5]  += p * v1.y;
                O[i][6]  += p * v1.z; O[i][7]  += p * v1.w;
                O[i][8]  += p * v2.x; O[i][9]  += p * v2.y;
                O[i][10] += p * v2.z; O[i][11] += p * v2.w;
                O[i][12] += p * v3.x; O[i][13] += p * v3.y;
                O[i][14] += p * v3.z; O[i][15] += p * v3.w;
            }
        }
    }

    // Epilogue: O / l -> g_attn[b*S + s][h*HD + c]
    #pragma unroll
    for (int i = 0; i < 4; i++) {
        int r = rg * 4 + i;
        float inv = 1.0f / rowl[r];
        int srow = qt * AQ + r;
        float* dst = outb + ((size_t)(b * SEQ + srow)) * DIM + h * HD + cg * 16;
        float4 o0 = make_float4(O[i][0] * inv, O[i][1] * inv, O[i][2] * inv, O[i][3] * inv);
        float4 o1 = make_float4(O[i][4] * inv, O[i][5] * inv, O[i][6] * inv, O[i][7] * inv);
        float4 o2 = make_float4(O[i][8] * inv, O[i][9] * inv, O[i][10] * inv, O[i][11] * inv);
        float4 o3 = make_float4(O[i][12] * inv, O[i][13] * inv, O[i][14] * inv, O[i][15] * inv);
        *(float4*)(dst + 0)  = o0;
        *(float4*)(dst + 4)  = o1;
        *(float4*)(dst + 8)  = o2;
        *(float4*)(dst + 12) = o3;
    }
}

// ----------------------------------------------------------------------------
// Host launcher
// ----------------------------------------------------------------------------
extern "C" void kernel_launch(void* const* d_in, const int* in_sizes, int n_in,
                              void* d_out, int out_size)
{
    // Input order: x, start_pos, freqs_cos, freqs_sin, mask, wq, wk, wv, wo,
    //              cache_k, cache_v. start_pos==0 -> mask/caches unused.
    const float* x  = (const float*)d_in[0];
    const float* fc = (const float*)d_in[2];
    const float* fs = (const float*)d_in[3];
    const float* wq = (const float*)d_in[5];
    const float* wk = (const float*)d_in[6];
    const float* wv = (const float*)d_in[7];
    const float* wo = (const float*)d_in[8];
    float* out = (float*)d_out;

    float *gq, *gk, *gv, *gattn;
    cudaGetSymbolAddress((void**)&gq, g_q);
    cudaGetSymbolAddress((void**)&gk, g_k);
    cudaGetSymbolAddress((void**)&gv, g_v);
    cudaGetSymbolAddress((void**)&gattn, g_attn);

    // QKV projections (epilogue splits heads into [B, nh, S, HD])
    sgemm_kernel<<<dim3(DIM / BN, MROWS / BM), 256>>>(x, wq, gq, MROWS, DIM, DIM, 1, NH);
    sgemm_kernel<<<dim3((NKVH * HD) / BN, MROWS / BM), 256>>>(x, wk, gk, MROWS, NKVH * HD, DIM, 1, NKVH);
    sgemm_kernel<<<dim3((NKVH * HD) / BN, MROWS / BM), 256>>>(x, wv, gv, MROWS, NKVH * HD, DIM, 1, NKVH);

    // RoPE on Q and K
    {
        size_t total = (size_t)BSZ * (NH + NKVH) * SEQ * 64;
        int blocks = (int)((total + 255) / 256);
        rope_kernel<<<blocks, 256>>>(gq, gk, fc, fs);
    }

    // Flash attention
    {
        const int smem = (AQ * HD + AK * HD + AK * HD + AQ * PS_STRIDE + 3 * AQ) * 4;
        cudaFuncSetAttribute(attn_kernel, cudaFuncAttributeMaxDynamicSharedMemorySize, smem);
        attn_kernel<<<dim3(SEQ / AQ, NH, BSZ), 256, smem>>>(gq, gk, gv, gattn);
    }

    // Output projection
    sgemm_kernel<<<dim3(DIM / BN, MROWS / BM), 256>>>(gattn, wo, out, MROWS, DIM, DIM, 0, 0);
}